// round 2
// baseline (speedup 1.0000x reference)
#include <cuda_runtime.h>
#include <math.h>

// Problem constants
#define BB 16
#define MM 2048
#define FD 128
#define QT 64
#define KT 64
#define SSTRIDE 132          // 128 + 4 pad (multiple of 4 -> float4 aligned)
#define SMEM_BYTES ((QT + KT) * SSTRIDE * 4)

// Scratch: normalized x, [B][M][FD]
__device__ float g_xnorm[BB * MM * FD];

// ---------------------------------------------------------------------------
// Kernel 1: L2-normalize each row of x (one warp per row, float4 per lane)
// ---------------------------------------------------------------------------
__global__ void normalize_kernel(const float* __restrict__ x) {
    int row  = blockIdx.x * 8 + (threadIdx.x >> 5);
    int lane = threadIdx.x & 31;
    if (row >= BB * MM) return;
    const float4* src = reinterpret_cast<const float4*>(x + (size_t)row * FD);
    float4 v = src[lane];
    float ss = v.x * v.x + v.y * v.y + v.z * v.z + v.w * v.w;
    #pragma unroll
    for (int o = 16; o > 0; o >>= 1) ss += __shfl_xor_sync(0xffffffffu, ss, o);
    float inv = 1.0f / fmaxf(sqrtf(ss), 1e-12f);
    float4 r = make_float4(v.x * inv, v.y * inv, v.z * inv, v.w * inv);
    reinterpret_cast<float4*>(g_xnorm + (size_t)row * FD)[lane] = r;
}

// top-2 update with jax tie-break (equal values -> lower index wins)
__device__ __forceinline__ void top2_update(float v, int k,
                                            float& v1, int& i1,
                                            float& v2, int& i2) {
    bool b1 = (v > v1) || (v == v1 && k < i1);
    bool b2 = (v > v2) || (v == v2 && k < i2);
    if (b1) { v2 = v1; i2 = i1; v1 = v; i1 = k; }
    else if (b2) { v2 = v; i2 = k; }
}

// ---------------------------------------------------------------------------
// Kernel 2: fused cosine-GEMM + streaming top-2 + symmetric scatter.
// Grid: (M/QT, B).  Block: 256 threads = 16 (tx, k-dim) x 16 (ty, q-dim).
// Each thread owns q rows {ty+16i} and k cols {tx+16j}, i,j in [0,4).
// ---------------------------------------------------------------------------
__global__ __launch_bounds__(256) void top2_kernel(float* __restrict__ out) {
    extern __shared__ float smem[];
    float* Qs = smem;                 // QT x SSTRIDE
    float* Ks = smem + QT * SSTRIDE;  // KT x SSTRIDE

    const int b     = blockIdx.y;
    const int qbase = blockIdx.x * QT;
    const float* Xb = g_xnorm + (size_t)b * MM * FD;

    const int tid = threadIdx.x;
    const int tx  = tid & 15;
    const int ty  = tid >> 4;

    // Load Q tile: 64x128 floats = 2048 float4 -> 8 per thread, coalesced.
    #pragma unroll
    for (int i = 0; i < 8; i++) {
        int idx = tid + i * 256;
        int r = idx >> 5, c4 = idx & 31;
        float4 v = reinterpret_cast<const float4*>(Xb + (size_t)(qbase + r) * FD)[c4];
        *reinterpret_cast<float4*>(Qs + r * SSTRIDE + c4 * 4) = v;
    }

    // Per-thread running top-2 for each of 4 owned q rows
    float v1[4], v2[4];
    int   i1[4], i2[4];
    #pragma unroll
    for (int i = 0; i < 4; i++) {
        v1[i] = -INFINITY; v2[i] = -INFINITY;
        i1[i] = 0x7fffffff; i2[i] = 0x7fffffff;
    }

    for (int kt = 0; kt < MM / KT; kt++) {
        const int kbase = kt * KT;
        __syncthreads();   // Ks reuse hazard (and first-iter Q/K store fence)
        #pragma unroll
        for (int i = 0; i < 8; i++) {
            int idx = tid + i * 256;
            int r = idx >> 5, c4 = idx & 31;
            float4 v = reinterpret_cast<const float4*>(Xb + (size_t)(kbase + r) * FD)[c4];
            *reinterpret_cast<float4*>(Ks + r * SSTRIDE + c4 * 4) = v;
        }
        __syncthreads();

        float acc[4][4];
        #pragma unroll
        for (int i = 0; i < 4; i++)
            #pragma unroll
            for (int j = 0; j < 4; j++) acc[i][j] = 0.0f;

        #pragma unroll 4
        for (int f = 0; f < FD; f += 4) {
            float4 qv[4], kv[4];
            #pragma unroll
            for (int i = 0; i < 4; i++)
                qv[i] = *reinterpret_cast<const float4*>(Qs + (ty + 16 * i) * SSTRIDE + f);
            #pragma unroll
            for (int j = 0; j < 4; j++)
                kv[j] = *reinterpret_cast<const float4*>(Ks + (tx + 16 * j) * SSTRIDE + f);
            #pragma unroll
            for (int i = 0; i < 4; i++) {
                #pragma unroll
                for (int j = 0; j < 4; j++) {
                    acc[i][j] += qv[i].x * kv[j].x;
                    acc[i][j] += qv[i].y * kv[j].y;
                    acc[i][j] += qv[i].z * kv[j].z;
                    acc[i][j] += qv[i].w * kv[j].w;
                }
            }
        }

        // Fold this tile's 4x4 dots into the running top-2
        #pragma unroll
        for (int i = 0; i < 4; i++) {
            int qg = qbase + ty + 16 * i;
            #pragma unroll
            for (int j = 0; j < 4; j++) {
                int kg = kbase + tx + 16 * j;
                float v = (kg == qg) ? 0.0f : acc[i][j];  // zeroed diagonal
                top2_update(v, kg, v1[i], i1[i], v2[i], i2[i]);
            }
        }
    }

    // Cross-thread top-2 reduction: 16 tx-threads per q row, 2 cands each.
    __syncthreads();
    float* cv = smem;                                  // [64][32]
    int*   ci = reinterpret_cast<int*>(smem + QT * 32); // [64][32]
    #pragma unroll
    for (int i = 0; i < 4; i++) {
        int q = ty + 16 * i;
        int base = q * 32 + tx * 2;
        cv[base]     = v1[i]; ci[base]     = i1[i];
        cv[base + 1] = v2[i]; ci[base + 1] = i2[i];
    }
    __syncthreads();

    if (tid < QT) {
        float V1 = -INFINITY, V2 = -INFINITY;
        int   I1 = 0x7fffffff, I2 = 0x7fffffff;
        #pragma unroll 8
        for (int t = 0; t < 32; t++) {
            float v = cv[tid * 32 + t];
            int   k = ci[tid * 32 + t];
            top2_update(v, k, V1, I1, V2, I2);
        }
        const int gq = qbase + tid;
        float* O = out + (size_t)b * MM * MM;
        // 0.5 * (S + S^T): forward + transpose contribution via atomics
        atomicAdd(O + (size_t)gq * MM + I1, 0.5f * V1);
        atomicAdd(O + (size_t)I1 * MM + gq, 0.5f * V1);
        atomicAdd(O + (size_t)gq * MM + I2, 0.5f * V2);
        atomicAdd(O + (size_t)I2 * MM + gq, 0.5f * V2);
    }
}

// ---------------------------------------------------------------------------
extern "C" void kernel_launch(void* const* d_in, const int* in_sizes, int n_in,
                              void* d_out, int out_size) {
    const float* x = (const float*)d_in[0];
    float* out = (float*)d_out;

    // Output is sparse: zero-fill, then scatter only top-2 entries.
    cudaMemsetAsync(out, 0, (size_t)out_size * sizeof(float));

    normalize_kernel<<<(BB * MM) / 8, 256>>>(x);

    cudaFuncSetAttribute(top2_kernel,
                         cudaFuncAttributeMaxDynamicSharedMemorySize, SMEM_BYTES);
    dim3 grid(MM / QT, BB);
    top2_kernel<<<grid, 256, SMEM_BYTES>>>(out);
}

// round 5
// speedup vs baseline: 1.2628x; 1.2628x over previous
#include <cuda_runtime.h>
#include <math.h>
#include <stdint.h>

// ---------------------------------------------------------------------------
// Problem constants
// ---------------------------------------------------------------------------
#define BB 16
#define MM 2048
#define FD 128
#define TS 128                       // tile size (rows per tile)
#define NT (MM / TS)                 // 16 tiles per batch
#define NPAIR (NT * (NT + 1) / 2)    // 136 tile pairs (i <= j)
#define SSTRIDE 132                  // 128 + 4 floats pad
#define SMEM_BYTES (2 * TS * SSTRIDE * 4)   // 135168 B

// Scratch (device globals; no allocation allowed)
__device__ __align__(128) float  g_xnorm[BB * MM * FD];            // 16 MB
__device__ __align__(128) float2 g_cand[BB * MM * 32];             // 8 MB: [b][m][slot16][2]

// ---------------------------------------------------------------------------
// Packed f32x2 FMA (sm_100+ base feature; NOT 'a'-gated)
// ---------------------------------------------------------------------------
__device__ __forceinline__ unsigned long long fma2(unsigned long long a,
                                                   unsigned long long b,
                                                   unsigned long long c) {
    unsigned long long d;
    asm("fma.rn.f32x2 %0, %1, %2, %3;" : "=l"(d) : "l"(a), "l"(b), "l"(c));
    return d;
}

__device__ __forceinline__ float fold2(unsigned long long v) {
    float lo = __uint_as_float((unsigned)(v & 0xffffffffull));
    float hi = __uint_as_float((unsigned)(v >> 32));
    return lo + hi;
}

// top-2 update, jax tie-break (equal value -> lower index). Candidates distinct.
__device__ __forceinline__ void top2_update(float v, int k,
                                            float& v1, int& i1, float& v2, int& i2) {
    bool b1 = (v > v1) || (v == v1 && k < i1);
    bool b2 = (v > v2) || (v == v2 && k < i2);
    if (b1)      { v2 = v1; i2 = i1; v1 = v; i1 = k; }
    else if (b2) { v2 = v;  i2 = k; }
}

// merge variant with index-dedup (butterfly reduction sees duplicate candidates)
__device__ __forceinline__ void top2_merge(float v, int k,
                                           float& v1, int& i1, float& v2, int& i2) {
    if (k == i1 || k == i2) return;
    top2_update(v, k, v1, i1, v2, i2);
}

// ---------------------------------------------------------------------------
// Kernel 1: L2-normalize each row (one warp per row)
// ---------------------------------------------------------------------------
__global__ void normalize_kernel(const float* __restrict__ x) {
    int row  = blockIdx.x * 8 + (threadIdx.x >> 5);
    int lane = threadIdx.x & 31;
    float4 v = reinterpret_cast<const float4*>(x + (size_t)row * FD)[lane];
    float ss = v.x * v.x + v.y * v.y + v.z * v.z + v.w * v.w;
    #pragma unroll
    for (int o = 16; o > 0; o >>= 1) ss += __shfl_xor_sync(0xffffffffu, ss, o);
    float inv = 1.0f / fmaxf(sqrtf(ss), 1e-12f);
    v.x *= inv; v.y *= inv; v.z *= inv; v.w *= inv;
    reinterpret_cast<float4*>(g_xnorm + (size_t)row * FD)[lane] = v;
}

// ---------------------------------------------------------------------------
// Kernel 2: symmetric tile-pair GEMM (FFMA2, 8x8 micro-tile) + per-tile top-2
// candidates (row-wise AND col-wise) into g_cand.
// Grid: (NPAIR, BB). Block 256 = 16(tx) x 16(ty).
// ---------------------------------------------------------------------------
__global__ void __launch_bounds__(256, 1) pair_kernel() {
    extern __shared__ float smem[];
    float* Qs = smem;                     // TS x SSTRIDE
    float* Ks = smem + TS * SSTRIDE;

    const int tid = threadIdx.x;
    const int tx  = tid & 15;
    const int ty  = tid >> 4;
    const int b   = blockIdx.y;

    // decode tile pair (i <= j)
    int t = blockIdx.x, ti = 0, n = NT;
    while (t >= n) { t -= n; n--; ti++; }
    const int tj = ti + t;
    const int ibase = ti * TS;
    const int jbase = tj * TS;

    const float* Xb = g_xnorm + (size_t)b * MM * FD;

    // Load Q tile (and K tile if distinct). 128 rows x 32 float4, coalesced.
    #pragma unroll
    for (int p = 0; p < 16; p++) {
        int idx = tid + p * 256;
        int r = idx >> 5, c4 = idx & 31;
        float4 v = reinterpret_cast<const float4*>(Xb + (size_t)(ibase + r) * FD)[c4];
        *reinterpret_cast<float4*>(Qs + r * SSTRIDE + c4 * 4) = v;
    }
    const float* Kt = (ti == tj) ? Qs : Ks;
    if (ti != tj) {
        #pragma unroll
        for (int p = 0; p < 16; p++) {
            int idx = tid + p * 256;
            int r = idx >> 5, c4 = idx & 31;
            float4 v = reinterpret_cast<const float4*>(Xb + (size_t)(jbase + r) * FD)[c4];
            *reinterpret_cast<float4*>(Ks + r * SSTRIDE + c4 * 4) = v;
        }
    }
    __syncthreads();

    // 8x8 micro-tile accumulation in packed f32x2 (pairs along f)
    unsigned long long acc2[8][8];
    #pragma unroll
    for (int i = 0; i < 8; i++)
        #pragma unroll
        for (int j = 0; j < 8; j++) acc2[i][j] = 0ull;

    #pragma unroll 2
    for (int f = 0; f < FD; f += 4) {
        ulonglong2 q2[8], k2[8];
        #pragma unroll
        for (int i = 0; i < 8; i++)
            q2[i] = *reinterpret_cast<const ulonglong2*>(Qs + (ty + 16 * i) * SSTRIDE + f);
        #pragma unroll
        for (int j = 0; j < 8; j++)
            k2[j] = *reinterpret_cast<const ulonglong2*>(Kt + (tx + 16 * j) * SSTRIDE + f);
        #pragma unroll
        for (int i = 0; i < 8; i++) {
            #pragma unroll
            for (int j = 0; j < 8; j++) {
                acc2[i][j] = fma2(q2[i].x, k2[j].x, acc2[i][j]);
                acc2[i][j] = fma2(q2[i].y, k2[j].y, acc2[i][j]);
            }
        }
    }

    float acc[8][8];
    #pragma unroll
    for (int i = 0; i < 8; i++)
        #pragma unroll
        for (int j = 0; j < 8; j++) acc[i][j] = fold2(acc2[i][j]);

    // diagonal tile: zero q==k entries (value 0 stays a legit candidate,
    // matching the reference's zeroed-diagonal adjacency)
    if (ti == tj && tx == ty) {
        #pragma unroll
        for (int i = 0; i < 8; i++) acc[i][i] = 0.0f;
    }

    // ---- Pass 1: row-wise top-2 (rows of tile ti, cols of tile tj) ----
    __syncthreads();
    float* cv = smem;                         // [128][32]
    int*   ci = reinterpret_cast<int*>(smem) + 128 * 32;
    #pragma unroll
    for (int i = 0; i < 8; i++) {
        float v1 = -INFINITY, v2 = -INFINITY;
        int   i1 = 0x7fffffff, i2 = 0x7fffffff;
        #pragma unroll
        for (int j = 0; j < 8; j++)
            top2_update(acc[i][j], jbase + tx + 16 * j, v1, i1, v2, i2);
        int r = ty + 16 * i;
        cv[r * 32 + tx * 2]     = v1; ci[r * 32 + tx * 2]     = i1;
        cv[r * 32 + tx * 2 + 1] = v2; ci[r * 32 + tx * 2 + 1] = i2;
    }
    __syncthreads();
    if (tid < 128) {
        float V1 = -INFINITY, V2 = -INFINITY;
        int   I1 = 0x7fffffff, I2 = 0x7fffffff;
        #pragma unroll 8
        for (int c = 0; c < 32; c++)
            top2_update(cv[tid * 32 + c], ci[tid * 32 + c], V1, I1, V2, I2);
        size_t base = ((size_t)(b * MM + ibase + tid) * 16 + tj) * 2;
        g_cand[base]     = make_float2(V1, __int_as_float(I1));
        g_cand[base + 1] = make_float2(V2, __int_as_float(I2));
    }

    // ---- Pass 2: col-wise top-2 (rows of tile tj, cols of tile ti) ----
    if (ti != tj) {
        __syncthreads();
        #pragma unroll
        for (int j = 0; j < 8; j++) {
            float v1 = -INFINITY, v2 = -INFINITY;
            int   i1 = 0x7fffffff, i2 = 0x7fffffff;
            #pragma unroll
            for (int i = 0; i < 8; i++)
                top2_update(acc[i][j], ibase + ty + 16 * i, v1, i1, v2, i2);
            int c = tx + 16 * j;
            cv[c * 32 + ty * 2]     = v1; ci[c * 32 + ty * 2]     = i1;
            cv[c * 32 + ty * 2 + 1] = v2; ci[c * 32 + ty * 2 + 1] = i2;
        }
        __syncthreads();
        if (tid < 128) {
            float V1 = -INFINITY, V2 = -INFINITY;
            int   I1 = 0x7fffffff, I2 = 0x7fffffff;
            #pragma unroll 8
            for (int c = 0; c < 32; c++)
                top2_update(cv[tid * 32 + c], ci[tid * 32 + c], V1, I1, V2, I2);
            size_t base = ((size_t)(b * MM + jbase + tid) * 16 + ti) * 2;
            g_cand[base]     = make_float2(V1, __int_as_float(I1));
            g_cand[base + 1] = make_float2(V2, __int_as_float(I2));
        }
    }
}

// ---------------------------------------------------------------------------
// Kernel 3: per-row reduction of 32 candidates -> top-2 -> symmetric scatter.
// One warp per row.
// ---------------------------------------------------------------------------
__global__ void reduce_kernel(float* __restrict__ out) {
    int row  = blockIdx.x * 8 + (threadIdx.x >> 5);
    int lane = threadIdx.x & 31;
    float2 c = g_cand[(size_t)row * 32 + lane];
    float v1 = c.x;          int i1 = __float_as_int(c.y);
    float v2 = -INFINITY;    int i2 = 0x7fffffff;
    #pragma unroll
    for (int o = 16; o > 0; o >>= 1) {
        float ov1 = __shfl_xor_sync(0xffffffffu, v1, o);
        float ov2 = __shfl_xor_sync(0xffffffffu, v2, o);
        int   oi1 = __shfl_xor_sync(0xffffffffu, i1, o);
        int   oi2 = __shfl_xor_sync(0xffffffffu, i2, o);
        top2_merge(ov1, oi1, v1, i1, v2, i2);
        top2_merge(ov2, oi2, v1, i1, v2, i2);
    }
    if (lane == 0) {
        int b = row >> 11, m = row & (MM - 1);
        float* O = out + (size_t)b * MM * MM;
        atomicAdd(O + (size_t)m * MM + i1, 0.5f * v1);
        atomicAdd(O + (size_t)i1 * MM + m, 0.5f * v1);
        atomicAdd(O + (size_t)m * MM + i2, 0.5f * v2);
        atomicAdd(O + (size_t)i2 * MM + m, 0.5f * v2);
    }
}

// ---------------------------------------------------------------------------
extern "C" void kernel_launch(void* const* d_in, const int* in_sizes, int n_in,
                              void* d_out, int out_size) {
    const float* x = (const float*)d_in[0];
    float* out = (float*)d_out;

    cudaMemsetAsync(out, 0, (size_t)out_size * sizeof(float));

    normalize_kernel<<<(BB * MM) / 8, 256>>>(x);

    cudaFuncSetAttribute(pair_kernel,
                         cudaFuncAttributeMaxDynamicSharedMemorySize, SMEM_BYTES);
    dim3 grid(NPAIR, BB);
    pair_kernel<<<grid, 256, SMEM_BYTES>>>();

    reduce_kernel<<<(BB * MM) / 8, 256>>>(out);
}

// round 8
// speedup vs baseline: 1.5500x; 1.2274x over previous
#include <cuda_runtime.h>
#include <math.h>
#include <stdint.h>

// ---------------------------------------------------------------------------
// Problem constants
// ---------------------------------------------------------------------------
#define BB 16
#define MM 2048
#define FD 128
#define TSQ 128                      // q rows per CTA
#define TSK 64                       // k cols per CTA (half tile)
#define NT (MM / TSQ)                // 16 tiles
#define NPAIR (NT * (NT + 1) / 2)    // 136 tile pairs (ti <= tj)
#define SSTRIDE 132                  // floats per smem row (128 + 4 pad)
#define SMEM_BYTES ((TSQ + TSK) * SSTRIDE * 4)   // 101376 B -> 2 CTAs/SM

// Scratch (device globals; no allocation allowed)
__device__ __align__(128) float  g_xnorm[BB * MM * FD];       // 16 MB
// Candidates: [b*M + row][slot(32)][2] float2 {val, idx-bits}
__device__ __align__(128) float2 g_cand[(size_t)BB * MM * 32 * 2];   // 16.8 MB

// ---------------------------------------------------------------------------
__device__ __forceinline__ unsigned long long fma2(unsigned long long a,
                                                   unsigned long long b,
                                                   unsigned long long c) {
    unsigned long long d;
    asm("fma.rn.f32x2 %0, %1, %2, %3;" : "=l"(d) : "l"(a), "l"(b), "l"(c));
    return d;
}

__device__ __forceinline__ float fold2(unsigned long long v) {
    float lo = __uint_as_float((unsigned)(v & 0xffffffffull));
    float hi = __uint_as_float((unsigned)(v >> 32));
    return lo + hi;
}

// top-2 update, jax tie-break (equal value -> lower index); candidates distinct
__device__ __forceinline__ void top2_update(float v, int k,
                                            float& v1, int& i1, float& v2, int& i2) {
    bool b1 = (v > v1) || (v == v1 && k < i1);
    bool b2 = (v > v2) || (v == v2 && k < i2);
    if (b1)      { v2 = v1; i2 = i1; v1 = v; i1 = k; }
    else if (b2) { v2 = v;  i2 = k; }
}

// butterfly-merge variant: partners carry identical winners -> dedup by index
__device__ __forceinline__ void top2_merge(float v, int k,
                                           float& v1, int& i1, float& v2, int& i2) {
    if (k == i1 || k == i2) return;
    top2_update(v, k, v1, i1, v2, i2);
}

// ---------------------------------------------------------------------------
// Kernel 1: L2-normalize each row (one warp per row)
// ---------------------------------------------------------------------------
__global__ void normalize_kernel(const float* __restrict__ x) {
    int row  = blockIdx.x * 8 + (threadIdx.x >> 5);
    int lane = threadIdx.x & 31;
    float4 v = reinterpret_cast<const float4*>(x + (size_t)row * FD)[lane];
    float ss = v.x * v.x + v.y * v.y + v.z * v.z + v.w * v.w;
    #pragma unroll
    for (int o = 16; o > 0; o >>= 1) ss += __shfl_xor_sync(0xffffffffu, ss, o);
    float inv = 1.0f / fmaxf(sqrtf(ss), 1e-12f);
    v.x *= inv; v.y *= inv; v.z *= inv; v.w *= inv;
    reinterpret_cast<float4*>(g_xnorm + (size_t)row * FD)[lane] = v;
}

// ---------------------------------------------------------------------------
// Kernel 2: symmetric tile-pair GEMM, 128(q) x 64(k) per CTA, 8x4 micro-tile.
// Grid: (NPAIR, 2, BB). Block 256 = 16(tx, k) x 16(ty, q). 2 CTAs/SM.
// Emits per-row top-2 candidates row-wise (pass 1) and col-wise (pass 2).
// ---------------------------------------------------------------------------
__global__ void __launch_bounds__(256, 2) pair_kernel() {
    extern __shared__ float smem[];
    float* Qs = smem;                      // TSQ x SSTRIDE
    float* Ks = smem + TSQ * SSTRIDE;      // TSK x SSTRIDE

    const int tid   = threadIdx.x;
    const int tx    = tid & 15;
    const int ty    = tid >> 4;
    const int chunk = blockIdx.y;          // which 64-col half of the k tile
    const int b     = blockIdx.z;

    // decode tile pair (ti <= tj)
    int t = blockIdx.x, ti = 0, n = NT;
    while (t >= n) { t -= n; n--; ti++; }
    const int tj    = ti + t;
    const int ibase = ti * TSQ;
    const int kbase = tj * TSQ + chunk * TSK;

    const float* Xb = g_xnorm + (size_t)b * MM * FD;

    // Load Q tile: 128 rows x 32 float4, coalesced (16 per thread)
    #pragma unroll
    for (int p = 0; p < 16; p++) {
        int idx = tid + p * 256;
        int r = idx >> 5, c4 = idx & 31;
        float4 v = reinterpret_cast<const float4*>(Xb + (size_t)(ibase + r) * FD)[c4];
        *reinterpret_cast<float4*>(Qs + r * SSTRIDE + c4 * 4) = v;
    }
    // Load K tile: 64 rows x 32 float4 (8 per thread)
    #pragma unroll
    for (int p = 0; p < 8; p++) {
        int idx = tid + p * 256;
        int r = idx >> 5, c4 = idx & 31;
        float4 v = reinterpret_cast<const float4*>(Xb + (size_t)(kbase + r) * FD)[c4];
        *reinterpret_cast<float4*>(Ks + r * SSTRIDE + c4 * 4) = v;
    }
    __syncthreads();

    // 8x4 micro-tile, packed-f32x2 accumulation (pairs along f).
    unsigned long long acc2[8][4];
    #pragma unroll
    for (int i = 0; i < 8; i++)
        #pragma unroll
        for (int j = 0; j < 4; j++) acc2[i][j] = 0ull;

    #pragma unroll 2
    for (int f = 0; f < FD; f += 4) {
        ulonglong2 k2[4];
        #pragma unroll
        for (int j = 0; j < 4; j++)
            k2[j] = *reinterpret_cast<const ulonglong2*>(Ks + (tx + 16 * j) * SSTRIDE + f);
        #pragma unroll
        for (int half = 0; half < 2; half++) {
            ulonglong2 q2[4];
            #pragma unroll
            for (int i = 0; i < 4; i++)
                q2[i] = *reinterpret_cast<const ulonglong2*>(
                    Qs + (ty + 16 * (half * 4 + i)) * SSTRIDE + f);
            #pragma unroll
            for (int i = 0; i < 4; i++) {
                #pragma unroll
                for (int j = 0; j < 4; j++) {
                    acc2[half * 4 + i][j] = fma2(q2[i].x, k2[j].x, acc2[half * 4 + i][j]);
                    acc2[half * 4 + i][j] = fma2(q2[i].y, k2[j].y, acc2[half * 4 + i][j]);
                }
            }
        }
    }

    float acc[8][4];
    #pragma unroll
    for (int i = 0; i < 8; i++)
        #pragma unroll
        for (int j = 0; j < 4; j++) acc[i][j] = fold2(acc2[i][j]);

    // zero the diagonal (only possible within diagonal tile pairs)
    if (ti == tj) {
        #pragma unroll
        for (int i = 0; i < 8; i++)
            #pragma unroll
            for (int j = 0; j < 4; j++)
                if (ty + 16 * i == chunk * TSK + tx + 16 * j) acc[i][j] = 0.0f;
    }

    float* cv = smem;                                     // [128][32]
    int*   ci = reinterpret_cast<int*>(smem) + 128 * 32;

    // ---- Pass 1: row-wise top-2 (q rows of ti vs this 64-col chunk) ----
    __syncthreads();   // done with tiles; reuse smem
    #pragma unroll
    for (int i = 0; i < 8; i++) {
        float v1 = -INFINITY, v2 = -INFINITY;
        int   i1 = 0x7fffffff, i2 = 0x7fffffff;
        #pragma unroll
        for (int j = 0; j < 4; j++)
            top2_update(acc[i][j], kbase + tx + 16 * j, v1, i1, v2, i2);
        int r = ty + 16 * i;
        cv[r * 32 + tx * 2]     = v1; ci[r * 32 + tx * 2]     = i1;
        cv[r * 32 + tx * 2 + 1] = v2; ci[r * 32 + tx * 2 + 1] = i2;
    }
    __syncthreads();
    if (tid < TSQ) {
        float V1 = -INFINITY, V2 = -INFINITY;
        int   I1 = 0x7fffffff, I2 = 0x7fffffff;
        #pragma unroll 8
        for (int c = 0; c < 32; c++)
            top2_update(cv[tid * 32 + c], ci[tid * 32 + c], V1, I1, V2, I2);
        size_t base = ((size_t)(b * MM + ibase + tid) * 32 + (2 * tj + chunk)) * 2;
        g_cand[base]     = make_float2(V1, __int_as_float(I1));
        g_cand[base + 1] = make_float2(V2, __int_as_float(I2));
    }

    // ---- Pass 2: col-wise top-2 (k rows of this chunk vs 128 q cols) ----
    if (ti != tj) {
        __syncthreads();
        #pragma unroll
        for (int j = 0; j < 4; j++) {
            float v1 = -INFINITY, v2 = -INFINITY;
            int   i1 = 0x7fffffff, i2 = 0x7fffffff;
            #pragma unroll
            for (int i = 0; i < 8; i++)
                top2_update(acc[i][j], ibase + ty + 16 * i, v1, i1, v2, i2);
            int c = tx + 16 * j;    // 0..63
            cv[c * 32 + ty * 2]     = v1; ci[c * 32 + ty * 2]     = i1;
            cv[c * 32 + ty * 2 + 1] = v2; ci[c * 32 + ty * 2 + 1] = i2;
        }
        __syncthreads();
        if (tid < TSK) {
            float V1 = -INFINITY, V2 = -INFINITY;
            int   I1 = 0x7fffffff, I2 = 0x7fffffff;
            #pragma unroll 8
            for (int c = 0; c < 32; c++)
                top2_update(cv[tid * 32 + c], ci[tid * 32 + c], V1, I1, V2, I2);
            size_t base = ((size_t)(b * MM + kbase + tid) * 32 + ti) * 2;
            g_cand[base]     = make_float2(V1, __int_as_float(I1));
            g_cand[base + 1] = make_float2(V2, __int_as_float(I2));
        }
    }
}

// ---------------------------------------------------------------------------
// Kernel 3: per-row reduce of candidate slots -> top-2 -> symmetric scatter.
// One warp per row; lane L owns slot L (2 candidates).
// Valid slots for row in tile t: [0, t) from pass-2, [2t, 32) from pass-1.
// ---------------------------------------------------------------------------
__global__ void reduce_kernel(float* __restrict__ out) {
    int row  = blockIdx.x * 8 + (threadIdx.x >> 5);
    int lane = threadIdx.x & 31;
    int m = row & (MM - 1);
    int t = m >> 7;

    float v1 = -INFINITY, v2 = -INFINITY;
    int   i1 = 0x7fffffff, i2 = 0x7fffffff;
    bool valid = (lane < t) || (lane >= 2 * t);
    if (valid) {
        float4 c = reinterpret_cast<const float4*>(g_cand)[(size_t)row * 32 + lane];
        v1 = c.x; i1 = __float_as_int(c.y);
        top2_update(c.z, __float_as_int(c.w), v1, i1, v2, i2);
    }
    #pragma unroll
    for (int o = 16; o > 0; o >>= 1) {
        float ov1 = __shfl_xor_sync(0xffffffffu, v1, o);
        float ov2 = __shfl_xor_sync(0xffffffffu, v2, o);
        int   oi1 = __shfl_xor_sync(0xffffffffu, i1, o);
        int   oi2 = __shfl_xor_sync(0xffffffffu, i2, o);
        top2_merge(ov1, oi1, v1, i1, v2, i2);
        top2_merge(ov2, oi2, v1, i1, v2, i2);
    }
    if (lane == 0) {
        int b = row >> 11;
        float* O = out + (size_t)b * MM * MM;
        atomicAdd(O + (size_t)m * MM + i1, 0.5f * v1);
        atomicAdd(O + (size_t)i1 * MM + m, 0.5f * v1);
        atomicAdd(O + (size_t)m * MM + i2, 0.5f * v2);
        atomicAdd(O + (size_t)i2 * MM + m, 0.5f * v2);
    }
}

// ---------------------------------------------------------------------------
extern "C" void kernel_launch(void* const* d_in, const int* in_sizes, int n_in,
                              void* d_out, int out_size) {
    const float* x = (const float*)d_in[0];
    float* out = (float*)d_out;

    cudaMemsetAsync(out, 0, (size_t)out_size * sizeof(float));

    normalize_kernel<<<(BB * MM) / 8, 256>>>(x);

    cudaFuncSetAttribute(pair_kernel,
                         cudaFuncAttributeMaxDynamicSharedMemorySize, SMEM_BYTES);
    dim3 grid(NPAIR, 2, BB);
    pair_kernel<<<grid, 256, SMEM_BYTES>>>();

    reduce_kernel<<<(BB * MM) / 8, 256>>>(out);
}